// round 7
// baseline (speedup 1.0000x reference)
#include <cuda_runtime.h>

// VectorQuantizer: x [8,4,32,32] f32, codebook [16384,4] f32
// d_out (f32): [0..32767] embed_st [8,4,32,32]; [32768] loss; [32769..40960] idx

#define FMUL __fmul_rn
#define FADD __fadd_rn
#define FFMA __fmaf_rn

typedef unsigned long long u64;
typedef unsigned int u32;

constexpr int N_PTS   = 8192;
constexpr int K_CODES = 16384;
constexpr int KSPLIT  = 64;
constexpr int KCHUNK  = K_CODES / KSPLIT;   // 256
constexpr int K2      = KCHUNK / 2;         // 128 packed code-pairs
constexpr int THREADS = 128;
constexpr int PPT     = 4;
constexpr int PPB     = THREADS * PPT;      // 512
constexpr int PGROUPS = N_PTS / PPB;        // 16
constexpr int SUB     = 8;                  // codes per argmin sub-block

// Reduce kernel: 8 lanes per point, 32 points per 256-thread block
constexpr int RBLK    = 256;
constexpr int PPB_R   = RBLK / 8;           // 32 points per block
constexpr int NRB     = N_PTS / PPB_R;      // 256 blocks
constexpr int SPL     = KSPLIT / 8;         // 8 splits per lane

// Scratch (__device__ globals: no allocations allowed)
__device__ u64      g_key [KSPLIT * N_PTS];   // (orderable dist bits << 32) | sub-block start
__device__ float    g_lsum[NRB];
__device__ unsigned g_ctr = 0;

// ---------- f32x2 packed helpers (bit-exact per lane) ----------
__device__ __forceinline__ u64 pk(float lo, float hi) {
    u64 r; asm("mov.b64 %0, {%1,%2};" : "=l"(r) : "f"(lo), "f"(hi)); return r;
}
__device__ __forceinline__ void upk(float& lo, float& hi, u64 v) {
    asm("mov.b64 {%0,%1}, %2;" : "=f"(lo), "=f"(hi) : "l"(v));
}
__device__ __forceinline__ u64 mul2(u64 a, u64 b) {
    u64 d; asm("mul.rn.f32x2 %0, %1, %2;" : "=l"(d) : "l"(a), "l"(b)); return d;
}
__device__ __forceinline__ u64 add2(u64 a, u64 b) {
    u64 d; asm("add.rn.f32x2 %0, %1, %2;" : "=l"(d) : "l"(a), "l"(b)); return d;
}
__device__ __forceinline__ u64 fma2(u64 a, u64 b, u64 c) {
    u64 d; asm("fma.rn.f32x2 %0, %1, %2, %3;" : "=l"(d) : "l"(a), "l"(b), "l"(c)); return d;
}

__device__ __forceinline__ float e2_of(float4 e) {
    return FADD(FADD(FADD(FMUL(e.x, e.x), FMUL(e.y, e.y)),
                     FMUL(e.z, e.z)), FMUL(e.w, e.w));
}

// Monotone float -> u32 (total order incl. negatives)
__device__ __forceinline__ u32 f2key(float f) {
    u32 b = __float_as_uint(f);
    return (b & 0x80000000u) ? ~b : (b | 0x80000000u);
}
__device__ __forceinline__ float key2f(u32 k) {
    u32 b = (k & 0x80000000u) ? (k & 0x7FFFFFFFu) : ~k;
    return __uint_as_float(b);
}

// ---------- distance kernel (unchanged from R6) ----------
__global__ __launch_bounds__(THREADS)
void vq_dist_kernel(const float* __restrict__ x, const float4* __restrict__ cb) {
    __shared__ ulonglong2 sAB[K2];   // {ex-pair, ey-pair}
    __shared__ ulonglong2 sCD[K2];   // {ez-pair, ew-pair}
    __shared__ u64        sE2[K2];

    const int ks = blockIdx.x;   // 0..63
    const int pg = blockIdx.y;   // 0..15
    const int k0 = ks * KCHUNK;

    {
        int i = threadIdx.x;     // exactly K2 == THREADS
        float4 e0 = cb[k0 + 2 * i];
        float4 e1 = cb[k0 + 2 * i + 1];
        sAB[i] = make_ulonglong2(pk(e0.x, e1.x), pk(e0.y, e1.y));
        sCD[i] = make_ulonglong2(pk(e0.z, e1.z), pk(e0.w, e1.w));
        sE2[i] = pk(e2_of(e0), e2_of(e1));
    }
    __syncthreads();

    u64 zx2[PPT], zy2[PPT], zz2[PPT], zw2[PPT], z2p[PPT];
    float best[PPT];
    int   bst [PPT];

    #pragma unroll
    for (int j = 0; j < PPT; j++) {
        int n  = pg * PPB + j * THREADS + threadIdx.x;
        int b  = n >> 10;
        int hw = n & 1023;
        const float* xp = x + b * 4096 + hw;
        float zx = xp[0], zy = xp[1024], zz = xp[2048], zw = xp[3072];
        float z2 = FADD(FADD(FADD(FMUL(zx, zx), FMUL(zy, zy)),
                             FMUL(zz, zz)), FMUL(zw, zw));
        zx2[j] = pk(zx, zx); zy2[j] = pk(zy, zy);
        zz2[j] = pk(zz, zz); zw2[j] = pk(zw, zw);
        z2p[j] = pk(z2, z2);
        best[j] = 3.4e38f;
        bst [j] = k0;
    }

    const u64 NEG2 = pk(-2.0f, -2.0f);

    #pragma unroll 4
    for (int sb = 0; sb < K2; sb += SUB / 2) {     // 4 packed steps = 8 codes
        float m[PPT];
        #pragma unroll
        for (int j = 0; j < PPT; j++) m[j] = 3.4e38f;

        #pragma unroll
        for (int t = 0; t < SUB / 2; t++) {
            ulonglong2 ab = sAB[sb + t];
            ulonglong2 cd = sCD[sb + t];
            u64 e2p = sE2[sb + t];
            #pragma unroll
            for (int j = 0; j < PPT; j++) {
                u64 dot = fma2(zw2[j], cd.y,
                          fma2(zz2[j], cd.x,
                          fma2(zy2[j], ab.y,
                          mul2(zx2[j], ab.x))));
                u64 d2 = fma2(NEG2, dot, add2(z2p[j], e2p));
                float d0, d1; upk(d0, d1, d2);
                m[j] = fminf(m[j], fminf(d0, d1));
            }
        }
        #pragma unroll
        for (int j = 0; j < PPT; j++)
            if (m[j] < best[j]) { best[j] = m[j]; bst[j] = k0 + 2 * sb; }
    }

    #pragma unroll
    for (int j = 0; j < PPT; j++) {
        int n = pg * PPB + j * THREADS + threadIdx.x;
        g_key[ks * N_PTS + n] = ((u64)f2key(best[j]) << 32) | (u32)bst[j];
    }
}

// ---------- reduce: 8 lanes/point key-min, exact idx, outputs + fused loss ----------
__global__ __launch_bounds__(RBLK)
void vq_reduce_kernel(const float* __restrict__ x, const float4* __restrict__ cb,
                      float* __restrict__ out) {
    const int tid  = threadIdx.x;
    const int p    = tid >> 3;           // 0..31 point within block
    const int sub  = tid & 7;            // 0..7 lane within point-group
    const int n    = blockIdx.x * PPB_R + p;

    // Each lane scans 8 splits (independent 8B loads, full MLP)
    u64 bk = ~0ull;
    #pragma unroll
    for (int i = 0; i < SPL; i++) {
        u64 k = g_key[(sub * SPL + i) * N_PTS + n];
        bk = (k < bk) ? k : bk;
    }
    // 8-lane min tree (groups of 8 are xor-closed within the warp).
    // min key == min dist; ties -> lowest sub-block start == first occurrence.
    #pragma unroll
    for (int o = 4; o > 0; o >>= 1) {
        u64 k = __shfl_xor_sync(0xffffffffu, bk, o);
        bk = (k < bk) ? k : bk;
    }

    __shared__ float pls[PPB_R];

    if (sub == 0) {
        float best = key2f((u32)(bk >> 32));
        int   bs   = (int)(u32)(bk & 0xFFFFFFFFu);

        int b  = n >> 10;
        int hw = n & 1023;
        const float* xp = x + b * 4096 + hw;
        float zx = xp[0], zy = xp[1024], zz = xp[2048], zw = xp[3072];
        float z2 = FADD(FADD(FADD(FMUL(zx, zx), FMUL(zy, zy)),
                             FMUL(zz, zz)), FMUL(zw, zw));

        // Re-scan the 8-code winning sub-block; first k with d == best (exact ops)
        int bi = bs;
        bool found = false;
        float4 eb = cb[bs];
        #pragma unroll
        for (int t = 0; t < SUB; t++) {
            float4 e = cb[bs + t];
            float dot = FFMA(zw, e.w, FFMA(zz, e.z, FFMA(zy, e.y, FMUL(zx, e.x))));
            float d   = FFMA(-2.0f, dot, FADD(z2, e2_of(e)));
            if (!found && d == best) { bi = bs + t; eb = e; found = true; }
        }

        float* op = out + b * 4096 + hw;
        op[0]    = eb.x;
        op[1024] = eb.y;
        op[2048] = eb.z;
        op[3072] = eb.w;
        out[32768 + 1 + n] = (float)bi;

        float dx = eb.x - zx, dy = eb.y - zy, dz = eb.z - zz, dw = eb.w - zw;
        pls[p] = dx * dx + dy * dy + dz * dz + dw * dw;
    }
    __syncthreads();

    if (tid == 0) {
        float s = 0.0f;
        #pragma unroll
        for (int i = 0; i < PPB_R; i++) s += pls[i];
        g_lsum[blockIdx.x] = s;          // deterministic per-block partial
        __threadfence();
        unsigned old = atomicAdd(&g_ctr, 1u);
        if (old == NRB - 1) {            // last block finalizes loss
            float part[8] = {0, 0, 0, 0, 0, 0, 0, 0};
            #pragma unroll
            for (int i = 0; i < NRB; i += 8) {
                #pragma unroll
                for (int w = 0; w < 8; w++) part[w] += g_lsum[i + w];
            }
            double acc = 0.0;
            #pragma unroll
            for (int w = 0; w < 8; w++) acc += (double)part[w];
            out[32768] = (float)(acc * (1.25 / 32768.0));   // (1+0.25)*mean
            g_ctr = 0;                   // self-reset for graph replay
        }
    }
}

extern "C" void kernel_launch(void* const* d_in, const int* in_sizes, int n_in,
                              void* d_out, int out_size) {
    const float*  x   = (const float*)d_in[0];
    const float4* cb  = (const float4*)d_in[1];
    float*        out = (float*)d_out;

    vq_dist_kernel<<<dim3(KSPLIT, PGROUPS), THREADS>>>(x, cb);
    vq_reduce_kernel<<<NRB, RBLK>>>(x, cb, out);
}

// round 8
// speedup vs baseline: 1.5422x; 1.5422x over previous
#include <cuda_runtime.h>

// VectorQuantizer: x [8,4,32,32] f32, codebook [16384,4] f32
// d_out (f32): [0..32767] embed_st [8,4,32,32]; [32768] loss; [32769..40960] idx

#define FMUL __fmul_rn
#define FADD __fadd_rn
#define FFMA __fmaf_rn

typedef unsigned long long u64;
typedef unsigned int u32;

constexpr int N_PTS   = 8192;
constexpr int K_CODES = 16384;
constexpr int KSPLIT  = 64;
constexpr int KCHUNK  = K_CODES / KSPLIT;   // 256
constexpr int K2      = KCHUNK / 2;         // 128 packed code-pairs
constexpr int THREADS = 128;
constexpr int PPT     = 4;
constexpr int PPB     = THREADS * PPT;      // 512
constexpr int PGROUPS = N_PTS / PPB;        // 16
constexpr int SUB     = 8;                  // codes per argmin sub-block

constexpr int RBLK    = 128;
constexpr int NRB     = N_PTS / RBLK;       // 64

// Scratch (__device__ globals: no allocations allowed)
// g_best[n] holds max over splits of ~key, key = (orderable-dist << 32) | subblock.
// max(~key) == min(key): min dist, ties -> lowest sub-block (first occurrence).
// Zero-initialized statically; reduce kernel resets to 0 each run (replay-safe).
__device__ u64      g_best[N_PTS];
__device__ float    g_lsum[NRB];
__device__ unsigned g_ctr = 0;

// ---------- f32x2 packed helpers (bit-exact per lane) ----------
__device__ __forceinline__ u64 pk(float lo, float hi) {
    u64 r; asm("mov.b64 %0, {%1,%2};" : "=l"(r) : "f"(lo), "f"(hi)); return r;
}
__device__ __forceinline__ void upk(float& lo, float& hi, u64 v) {
    asm("mov.b64 {%0,%1}, %2;" : "=f"(lo), "=f"(hi) : "l"(v));
}
__device__ __forceinline__ u64 mul2(u64 a, u64 b) {
    u64 d; asm("mul.rn.f32x2 %0, %1, %2;" : "=l"(d) : "l"(a), "l"(b)); return d;
}
__device__ __forceinline__ u64 add2(u64 a, u64 b) {
    u64 d; asm("add.rn.f32x2 %0, %1, %2;" : "=l"(d) : "l"(a), "l"(b)); return d;
}
__device__ __forceinline__ u64 fma2(u64 a, u64 b, u64 c) {
    u64 d; asm("fma.rn.f32x2 %0, %1, %2, %3;" : "=l"(d) : "l"(a), "l"(b), "l"(c)); return d;
}

__device__ __forceinline__ float e2_of(float4 e) {
    return FADD(FADD(FADD(FMUL(e.x, e.x), FMUL(e.y, e.y)),
                     FMUL(e.z, e.z)), FMUL(e.w, e.w));
}

// Monotone float -> u32 (total order incl. negatives)
__device__ __forceinline__ u32 f2key(float f) {
    u32 b = __float_as_uint(f);
    return (b & 0x80000000u) ? ~b : (b | 0x80000000u);
}
__device__ __forceinline__ float key2f(u32 k) {
    u32 b = (k & 0x80000000u) ? (k & 0x7FFFFFFFu) : ~k;
    return __uint_as_float(b);
}

// ---------- distance kernel (R6 body; stores replaced by atomicMax fold) ----------
__global__ __launch_bounds__(THREADS)
void vq_dist_kernel(const float* __restrict__ x, const float4* __restrict__ cb) {
    __shared__ ulonglong2 sAB[K2];   // {ex-pair, ey-pair}
    __shared__ ulonglong2 sCD[K2];   // {ez-pair, ew-pair}
    __shared__ u64        sE2[K2];

    const int ks = blockIdx.x;   // 0..63
    const int pg = blockIdx.y;   // 0..15
    const int k0 = ks * KCHUNK;

    {
        int i = threadIdx.x;     // exactly K2 == THREADS
        float4 e0 = cb[k0 + 2 * i];
        float4 e1 = cb[k0 + 2 * i + 1];
        sAB[i] = make_ulonglong2(pk(e0.x, e1.x), pk(e0.y, e1.y));
        sCD[i] = make_ulonglong2(pk(e0.z, e1.z), pk(e0.w, e1.w));
        sE2[i] = pk(e2_of(e0), e2_of(e1));
    }
    __syncthreads();

    u64 zx2[PPT], zy2[PPT], zz2[PPT], zw2[PPT], z2p[PPT];
    float best[PPT];
    int   bst [PPT];

    #pragma unroll
    for (int j = 0; j < PPT; j++) {
        int n  = pg * PPB + j * THREADS + threadIdx.x;
        int b  = n >> 10;
        int hw = n & 1023;
        const float* xp = x + b * 4096 + hw;
        float zx = xp[0], zy = xp[1024], zz = xp[2048], zw = xp[3072];
        float z2 = FADD(FADD(FADD(FMUL(zx, zx), FMUL(zy, zy)),
                             FMUL(zz, zz)), FMUL(zw, zw));
        zx2[j] = pk(zx, zx); zy2[j] = pk(zy, zy);
        zz2[j] = pk(zz, zz); zw2[j] = pk(zw, zw);
        z2p[j] = pk(z2, z2);
        best[j] = 3.4e38f;
        bst [j] = k0;
    }

    const u64 NEG2 = pk(-2.0f, -2.0f);

    #pragma unroll 4
    for (int sb = 0; sb < K2; sb += SUB / 2) {     // 4 packed steps = 8 codes
        float m[PPT];
        #pragma unroll
        for (int j = 0; j < PPT; j++) m[j] = 3.4e38f;

        #pragma unroll
        for (int t = 0; t < SUB / 2; t++) {
            ulonglong2 ab = sAB[sb + t];
            ulonglong2 cd = sCD[sb + t];
            u64 e2p = sE2[sb + t];
            #pragma unroll
            for (int j = 0; j < PPT; j++) {
                u64 dot = fma2(zw2[j], cd.y,
                          fma2(zz2[j], cd.x,
                          fma2(zy2[j], ab.y,
                          mul2(zx2[j], ab.x))));
                u64 d2 = fma2(NEG2, dot, add2(z2p[j], e2p));
                float d0, d1; upk(d0, d1, d2);
                m[j] = fminf(m[j], fminf(d0, d1));
            }
        }
        #pragma unroll
        for (int j = 0; j < PPT; j++)
            if (m[j] < best[j]) { best[j] = m[j]; bst[j] = k0 + 2 * sb; }
    }

    #pragma unroll
    for (int j = 0; j < PPT; j++) {
        int n = pg * PPB + j * THREADS + threadIdx.x;
        u64 key = ((u64)f2key(best[j]) << 32) | (u32)bst[j];
        atomicMax(&g_best[n], ~key);     // REDG.MAX.64: order-independent fold
    }
}

// ---------- reduce: 1 thread/point, exact idx, outputs + fused loss ----------
__global__ __launch_bounds__(RBLK)
void vq_reduce_kernel(const float* __restrict__ x, const float4* __restrict__ cb,
                      float* __restrict__ out) {
    const int n = blockIdx.x * RBLK + threadIdx.x;

    u64 bk = ~g_best[n];
    g_best[n] = 0;                       // restore invariant for next graph replay

    float best = key2f((u32)(bk >> 32));
    int   bs   = (int)(u32)(bk & 0xFFFFFFFFu);

    int b  = n >> 10;
    int hw = n & 1023;
    const float* xp = x + b * 4096 + hw;
    float zx = xp[0], zy = xp[1024], zz = xp[2048], zw = xp[3072];
    float z2 = FADD(FADD(FADD(FMUL(zx, zx), FMUL(zy, zy)),
                         FMUL(zz, zz)), FMUL(zw, zw));

    // Re-scan the 8-code winning sub-block; first k with d == best (exact ops)
    int bi = bs;
    bool found = false;
    float4 eb = cb[bs];
    #pragma unroll
    for (int t = 0; t < SUB; t++) {
        float4 e = cb[bs + t];
        float dot = FFMA(zw, e.w, FFMA(zz, e.z, FFMA(zy, e.y, FMUL(zx, e.x))));
        float d   = FFMA(-2.0f, dot, FADD(z2, e2_of(e)));
        if (!found && d == best) { bi = bs + t; eb = e; found = true; }
    }

    float* op = out + b * 4096 + hw;
    op[0]    = eb.x;
    op[1024] = eb.y;
    op[2048] = eb.z;
    op[3072] = eb.w;
    out[32768 + 1 + n] = (float)bi;

    float dx = eb.x - zx, dy = eb.y - zy, dz = eb.z - zz, dw = eb.w - zw;
    float ls = dx * dx + dy * dy + dz * dz + dw * dw;

    #pragma unroll
    for (int o = 16; o > 0; o >>= 1)
        ls += __shfl_down_sync(0xffffffffu, ls, o);

    __shared__ float wsum[RBLK / 32];
    if ((threadIdx.x & 31) == 0) wsum[threadIdx.x >> 5] = ls;
    __syncthreads();
    if (threadIdx.x == 0) {
        float s = 0.0f;
        #pragma unroll
        for (int w = 0; w < RBLK / 32; w++) s += wsum[w];
        g_lsum[blockIdx.x] = s;          // deterministic per-block partial
        __threadfence();
        unsigned old = atomicAdd(&g_ctr, 1u);
        if (old == NRB - 1) {            // last block finalizes loss
            float part[8] = {0, 0, 0, 0, 0, 0, 0, 0};
            #pragma unroll
            for (int i = 0; i < NRB; i += 8) {
                #pragma unroll
                for (int w = 0; w < 8; w++) part[w] += g_lsum[i + w];
            }
            double acc = 0.0;
            #pragma unroll
            for (int w = 0; w < 8; w++) acc += (double)part[w];
            out[32768] = (float)(acc * (1.25 / 32768.0));   // (1+0.25)*mean
            g_ctr = 0;                   // self-reset for graph replay
        }
    }
}

extern "C" void kernel_launch(void* const* d_in, const int* in_sizes, int n_in,
                              void* d_out, int out_size) {
    const float*  x   = (const float*)d_in[0];
    const float4* cb  = (const float4*)d_in[1];
    float*        out = (float*)d_out;

    vq_dist_kernel<<<dim3(KSPLIT, PGROUPS), THREADS>>>(x, cb);
    vq_reduce_kernel<<<NRB, RBLK>>>(x, cb, out);
}

// round 9
// speedup vs baseline: 1.6376x; 1.0619x over previous
#include <cuda_runtime.h>

// VectorQuantizer: x [8,4,32,32] f32, codebook [16384,4] f32
// d_out (f32): [0..32767] embed_st [8,4,32,32]; [32768] loss; [32769..40960] idx

#define FMUL __fmul_rn
#define FADD __fadd_rn
#define FFMA __fmaf_rn

typedef unsigned long long u64;
typedef unsigned int u32;

constexpr int N_PTS   = 8192;
constexpr int K_CODES = 16384;
constexpr int KSPLIT  = 128;
constexpr int KCHUNK  = K_CODES / KSPLIT;   // 128
constexpr int K2      = KCHUNK / 2;         // 64 packed code-pairs
constexpr int THREADS = 128;
constexpr int PPT     = 4;
constexpr int PPB     = THREADS * PPT;      // 512
constexpr int PGROUPS = N_PTS / PPB;        // 16
constexpr int SUB     = 8;                  // codes per argmin sub-block

constexpr int RBLK    = 128;
constexpr int NRB     = N_PTS / RBLK;       // 64

// Scratch (__device__ globals: no allocations allowed)
// g_best[n] holds max over splits of ~key, key = (orderable-dist << 32) | subblock.
// max(~key) == min(key): min dist, ties -> lowest sub-block (first occurrence).
// Zero-initialized statically; reduce kernel resets to 0 each run (replay-safe).
__device__ u64      g_best[N_PTS];
__device__ float    g_lsum[NRB];
__device__ unsigned g_ctr = 0;

// ---------- f32x2 packed helpers (bit-exact per lane) ----------
__device__ __forceinline__ u64 pk(float lo, float hi) {
    u64 r; asm("mov.b64 %0, {%1,%2};" : "=l"(r) : "f"(lo), "f"(hi)); return r;
}
__device__ __forceinline__ void upk(float& lo, float& hi, u64 v) {
    asm("mov.b64 {%0,%1}, %2;" : "=f"(lo), "=f"(hi) : "l"(v));
}
__device__ __forceinline__ u64 mul2(u64 a, u64 b) {
    u64 d; asm("mul.rn.f32x2 %0, %1, %2;" : "=l"(d) : "l"(a), "l"(b)); return d;
}
__device__ __forceinline__ u64 add2(u64 a, u64 b) {
    u64 d; asm("add.rn.f32x2 %0, %1, %2;" : "=l"(d) : "l"(a), "l"(b)); return d;
}
__device__ __forceinline__ u64 fma2(u64 a, u64 b, u64 c) {
    u64 d; asm("fma.rn.f32x2 %0, %1, %2, %3;" : "=l"(d) : "l"(a), "l"(b), "l"(c)); return d;
}

__device__ __forceinline__ float e2_of(float4 e) {
    return FADD(FADD(FADD(FMUL(e.x, e.x), FMUL(e.y, e.y)),
                     FMUL(e.z, e.z)), FMUL(e.w, e.w));
}

// Monotone float -> u32 (total order incl. negatives)
__device__ __forceinline__ u32 f2key(float f) {
    u32 b = __float_as_uint(f);
    return (b & 0x80000000u) ? ~b : (b | 0x80000000u);
}
__device__ __forceinline__ float key2f(u32 k) {
    u32 b = (k & 0x80000000u) ? (k & 0x7FFFFFFFu) : ~k;
    return __uint_as_float(b);
}

// ---------- distance kernel ----------
__global__ __launch_bounds__(THREADS)
void vq_dist_kernel(const float* __restrict__ x, const float4* __restrict__ cb) {
    __shared__ ulonglong2 sAB[K2];   // {ex-pair, ey-pair}
    __shared__ ulonglong2 sCD[K2];   // {ez-pair, ew-pair}
    __shared__ u64        sE2[K2];

    const int ks = blockIdx.x;   // 0..127
    const int pg = blockIdx.y;   // 0..15
    const int k0 = ks * KCHUNK;

    if (threadIdx.x < K2) {
        int i = threadIdx.x;
        float4 e0 = cb[k0 + 2 * i];
        float4 e1 = cb[k0 + 2 * i + 1];
        sAB[i] = make_ulonglong2(pk(e0.x, e1.x), pk(e0.y, e1.y));
        sCD[i] = make_ulonglong2(pk(e0.z, e1.z), pk(e0.w, e1.w));
        sE2[i] = pk(e2_of(e0), e2_of(e1));
    }
    __syncthreads();

    u64 zx2[PPT], zy2[PPT], zz2[PPT], zw2[PPT], z2p[PPT];
    float best[PPT];
    int   bst [PPT];

    #pragma unroll
    for (int j = 0; j < PPT; j++) {
        int n  = pg * PPB + j * THREADS + threadIdx.x;
        int b  = n >> 10;
        int hw = n & 1023;
        const float* xp = x + b * 4096 + hw;
        float zx = xp[0], zy = xp[1024], zz = xp[2048], zw = xp[3072];
        float z2 = FADD(FADD(FADD(FMUL(zx, zx), FMUL(zy, zy)),
                             FMUL(zz, zz)), FMUL(zw, zw));
        zx2[j] = pk(zx, zx); zy2[j] = pk(zy, zy);
        zz2[j] = pk(zz, zz); zw2[j] = pk(zw, zw);
        z2p[j] = pk(z2, z2);
        best[j] = 3.4e38f;
        bst [j] = k0;
    }

    const u64 NEG2 = pk(-2.0f, -2.0f);

    #pragma unroll 4
    for (int sb = 0; sb < K2; sb += SUB / 2) {     // 4 packed steps = 8 codes
        float m[PPT];
        #pragma unroll
        for (int j = 0; j < PPT; j++) m[j] = 3.4e38f;

        #pragma unroll
        for (int t = 0; t < SUB / 2; t++) {
            ulonglong2 ab = sAB[sb + t];
            ulonglong2 cd = sCD[sb + t];
            u64 e2p = sE2[sb + t];
            #pragma unroll
            for (int j = 0; j < PPT; j++) {
                u64 dot = fma2(zw2[j], cd.y,
                          fma2(zz2[j], cd.x,
                          fma2(zy2[j], ab.y,
                          mul2(zx2[j], ab.x))));
                u64 d2 = fma2(NEG2, dot, add2(z2p[j], e2p));
                float d0, d1; upk(d0, d1, d2);
                m[j] = fminf(m[j], fminf(d0, d1));
            }
        }
        #pragma unroll
        for (int j = 0; j < PPT; j++)
            if (m[j] < best[j]) { best[j] = m[j]; bst[j] = k0 + 2 * sb; }
    }

    #pragma unroll
    for (int j = 0; j < PPT; j++) {
        int n = pg * PPB + j * THREADS + threadIdx.x;
        u64 key = ((u64)f2key(best[j]) << 32) | (u32)bst[j];
        atomicMax(&g_best[n], ~key);     // REDG.MAX.64: order-independent fold
    }
}

// ---------- reduce: 1 thread/point, exact idx, outputs + fused loss ----------
__global__ __launch_bounds__(RBLK)
void vq_reduce_kernel(const float* __restrict__ x, const float4* __restrict__ cb,
                      float* __restrict__ out) {
    const int n = blockIdx.x * RBLK + threadIdx.x;

    u64 bk = ~g_best[n];
    g_best[n] = 0;                       // restore invariant for next graph replay

    float best = key2f((u32)(bk >> 32));
    int   bs   = (int)(u32)(bk & 0xFFFFFFFFu);

    int b  = n >> 10;
    int hw = n & 1023;
    const float* xp = x + b * 4096 + hw;
    float zx = xp[0], zy = xp[1024], zz = xp[2048], zw = xp[3072];
    float z2 = FADD(FADD(FADD(FMUL(zx, zx), FMUL(zy, zy)),
                         FMUL(zz, zz)), FMUL(zw, zw));

    // Re-scan the 8-code winning sub-block; first k with d == best (exact ops)
    int bi = bs;
    bool found = false;
    float4 eb = cb[bs];
    #pragma unroll
    for (int t = 0; t < SUB; t++) {
        float4 e = cb[bs + t];
        float dot = FFMA(zw, e.w, FFMA(zz, e.z, FFMA(zy, e.y, FMUL(zx, e.x))));
        float d   = FFMA(-2.0f, dot, FADD(z2, e2_of(e)));
        if (!found && d == best) { bi = bs + t; eb = e; found = true; }
    }

    float* op = out + b * 4096 + hw;
    op[0]    = eb.x;
    op[1024] = eb.y;
    op[2048] = eb.z;
    op[3072] = eb.w;
    out[32768 + 1 + n] = (float)bi;

    float dx = eb.x - zx, dy = eb.y - zy, dz = eb.z - zz, dw = eb.w - zw;
    float ls = dx * dx + dy * dy + dz * dz + dw * dw;

    #pragma unroll
    for (int o = 16; o > 0; o >>= 1)
        ls += __shfl_down_sync(0xffffffffu, ls, o);

    __shared__ float wsum[RBLK / 32];
    if ((threadIdx.x & 31) == 0) wsum[threadIdx.x >> 5] = ls;
    __syncthreads();
    if (threadIdx.x == 0) {
        float s = 0.0f;
        #pragma unroll
        for (int w = 0; w < RBLK / 32; w++) s += wsum[w];
        g_lsum[blockIdx.x] = s;          // deterministic per-block partial
        __threadfence();
        unsigned old = atomicAdd(&g_ctr, 1u);
        if (old == NRB - 1) {            // last block finalizes loss
            float part[8] = {0, 0, 0, 0, 0, 0, 0, 0};
            #pragma unroll
            for (int i = 0; i < NRB; i += 8) {
                #pragma unroll
                for (int w = 0; w < 8; w++) part[w] += g_lsum[i + w];
            }
            double acc = 0.0;
            #pragma unroll
            for (int w = 0; w < 8; w++) acc += (double)part[w];
            out[32768] = (float)(acc * (1.25 / 32768.0));   // (1+0.25)*mean
            g_ctr = 0;                   // self-reset for graph replay
        }
    }
}

extern "C" void kernel_launch(void* const* d_in, const int* in_sizes, int n_in,
                              void* d_out, int out_size) {
    const float*  x   = (const float*)d_in[0];
    const float4* cb  = (const float4*)d_in[1];
    float*        out = (float*)d_out;

    vq_dist_kernel<<<dim3(KSPLIT, PGROUPS), THREADS>>>(x, cb);
    vq_reduce_kernel<<<NRB, RBLK>>>(x, cb, out);
}